// round 15
// baseline (speedup 1.0000x reference)
#include <cuda_runtime.h>
#include <cuda_bf16.h>

// ContrastiveLoss on GB300 — symmetric-triangular 3-pass bf16-split HMMA GEMM,
// SINGLE KERNEL. R15: k_rows is fused into k_main via per-row-band completion
// counters. Each band b (128 rows) has exactly 32 writer tiles; the tile whose
// atomicAdd(g_cnt[b]) reaches 32 runs band b's reduction in-kernel (overlapped
// with other tiles' compute). Final band-processor writes out[] and resets all
// global counters (self-cleaning across graph replays; zero-init covers call 1).
//
//   k_main : 528 tiles (off-diag first, diag last). 3-pass exact bf16 split
//            with pair-scoped barriers around the per-pair B-lo reload (R14).
//            Fused epilogue; MUFU ex2; row+col stats -> float4 partials
//            g_part[row][colblock]; g_pos scatter; then band-completion
//            tracking + in-kernel per-band reduction (one warp per row,
//            16 rows/warp) + final out[] write.

#define NTOT 4096
#define NH   2048
#define FD   128
#define KCLS 32
#define TEMPC 0.01f

__device__ float4        g_part[NTOT][32];   // x=full y=same z=S w=mxenc(bits)
__device__ float         g_pos[NTOT][128];
__device__ float         g_loss;
__device__ int           g_corr;
__device__ int           g_np;
__device__ unsigned int  g_cnt[32];          // per-band writer counters
__device__ unsigned int  g_bdone;            // bands reduced

__device__ __forceinline__ unsigned int encf(float f) {
    unsigned int u = __float_as_uint(f);
    return (u & 0x80000000u) ? ~u : (u | 0x80000000u);
}
__device__ __forceinline__ float decf(unsigned int v) {
    unsigned int u = (v & 0x80000000u) ? (v & 0x7FFFFFFFu) : ~v;
    return __uint_as_float(u);
}

__device__ unsigned sniff_ov(const unsigned char* __restrict__ ovraw) {
    const unsigned* u32p = (const unsigned*)ovraw;
    bool allF = true, anyF = false;
    #pragma unroll
    for (int c = 0; c < 8; c++) {
        unsigned u = u32p[c];
        if (u != 0u && u != 0x3F800000u) allF = false;
        if (u == 0x3F800000u) anyF = true;
    }
    int mode;
    if (allF && anyF) mode = 2;
    else {
        bool oddNZ = false;
        for (int i = 0; i < 32; i++) if ((i & 3) && ovraw[i]) oddNZ = true;
        mode = oddNZ ? 0 : 1;
    }
    unsigned m = 0;
    for (int c = 0; c < 32; c++) {
        bool ov;
        if (mode == 0)      ov = ovraw[c] != 0;
        else if (mode == 1) ov = ((const int*)ovraw)[c] != 0;
        else                ov = ((const float*)ovraw)[c] != 0.f;
        m |= (ov ? 1u : 0u) << c;
    }
    return m;
}

__device__ __forceinline__ int labelOf(int i, unsigned ovm) {
    if (i < NH) return i >> 6;
    int c = (i - NH) >> 6;
    if ((ovm >> c) & 1u) return c;
    return KCLS + __popc((~ovm) & ((1u << c) - 1u));
}

// ---------------- helpers ----------------

__device__ __forceinline__ unsigned smem_u32(const void* p) {
    unsigned a;
    asm("{ .reg .u64 t; cvta.to.shared.u64 t, %1; cvt.u32.u64 %0, t; }"
        : "=r"(a) : "l"(p));
    return a;
}

#define LDSM4(r, a) \
    asm volatile("ldmatrix.sync.aligned.m8n8.x4.shared.b16 {%0,%1,%2,%3}, [%4];" \
        : "=r"((r)[0]), "=r"((r)[1]), "=r"((r)[2]), "=r"((r)[3]) : "r"(a))

#define MMA(c, a, b0, b1) \
    asm volatile("mma.sync.aligned.m16n8k16.row.col.f32.bf16.bf16.f32 " \
        "{%0,%1,%2,%3}, {%4,%5,%6,%7}, {%8,%9}, {%0,%1,%2,%3};" \
        : "+f"((c)[0]), "+f"((c)[1]), "+f"((c)[2]), "+f"((c)[3]) \
        : "r"((a)[0]), "r"((a)[1]), "r"((a)[2]), "r"((a)[3]), "r"(b0), "r"(b1))

// Pair-scoped barrier: warps w and w+4 (same n0 / same B slice), 64 threads.
#define PAIR_BAR(pairid) \
    asm volatile("bar.sync %0, 64;" :: "r"(1 + (pairid)) : "memory")

__device__ __forceinline__ unsigned pack2(float a, float b) {
    __nv_bfloat162 t = __floats2bfloat162_rn(a, b);
    return *(unsigned*)&t;
}

__device__ __forceinline__ unsigned swz(int row, int kq) {
    return (unsigned)row * 256u
         + ((((unsigned)(kq >> 3)) ^ ((unsigned)row & 7u)) << 4)
         + (((unsigned)kq & 7u) << 1);
}

__device__ __forceinline__ void cvt_hilo(float4 v, uint2& hi, uint2& lo) {
    __nv_bfloat16 h0 = __float2bfloat16(v.x);
    __nv_bfloat16 h1 = __float2bfloat16(v.y);
    __nv_bfloat16 h2 = __float2bfloat16(v.z);
    __nv_bfloat16 h3 = __float2bfloat16(v.w);
    __nv_bfloat162 t01; t01.x = h0; t01.y = h1;
    __nv_bfloat162 t23; t23.x = h2; t23.y = h3;
    hi = make_uint2(*(unsigned*)&t01, *(unsigned*)&t23);
    lo = make_uint2(pack2(v.x - __bfloat162float(h0), v.y - __bfloat162float(h1)),
                    pack2(v.z - __bfloat162float(h2), v.w - __bfloat162float(h3)));
}

// MUFU-based exp: comparisons use raw x; approx only perturbs sums ~1e-6.
__device__ __forceinline__ float fast_exp(float x) {
    float r;
    asm("ex2.approx.ftz.f32 %0, %1;" : "=f"(r) : "f"(x * 1.44269504f));
    return r;
}

// ---------------- main kernel ----------------

#define SM_AHI  0
#define SM_ALO  32768
#define SM_B    65536
#define SM_LABC 98304
#define SM_LABR 98432
#define SM_RED  98560                   // row arrays: 4 x 512B
#define SM_RED2 (98560 + 2048)          // col arrays: 4 x 512B
#define SM_TOTAL (98560 + 4096)

__global__ void __launch_bounds__(256, 2)
k_main(const float* __restrict__ f1, const float* __restrict__ f2,
       const unsigned char* __restrict__ ovraw, float* out, int out_size) {
    // Decode: indices [0,496) = strict-upper off-diag pairs, [496,528) = diag.
    int bx, by;
    if (blockIdx.x >= 496) {
        by = blockIdx.x - 496; bx = by;
    } else {
        int tt0 = blockIdx.x; by = 0;
        while (tt0 >= 31 - by) { tt0 -= 31 - by; by++; }
        bx = by + 1 + tt0;
    }
    const bool diag = (bx == by);

    extern __shared__ char smc[];
    unsigned sbase = smem_u32(smc);
    float* s_full = (float*)(smc + SM_RED);
    float* s_same = s_full + 128;
    float* s_S    = s_same + 128;
    unsigned* s_mx = (unsigned*)(s_S + 128);
    float* c_full = (float*)(smc + SM_RED2);
    float* c_same = c_full + 128;
    float* c_S    = c_same + 128;
    unsigned* c_mx = (unsigned*)(c_S + 128);
    __shared__ unsigned s_ovm;
    __shared__ int s_todo[2];
    __shared__ int s_nt;
    __shared__ float r_l[8];
    __shared__ int   r_c[8];
    __shared__ int   r_n[8];

    const int tid = threadIdx.x, wid = tid >> 5, lane = tid & 31;
    const int rowbase = by << 7, colbase = bx << 7;
    const int m0 = (wid >> 2) << 6;
    const int n0 = (wid & 3) << 5;
    const int pairid = wid & 3;

    if (tid == 0) s_ovm = sniff_ov(ovraw);
    __syncthreads();
    const unsigned ovm = s_ovm;

    if (tid < 128) {
        smc[SM_LABC + tid] = (char)labelOf(colbase + tid, ovm);
        smc[SM_LABR + tid] = (char)labelOf(rowbase + tid, ovm);
        s_full[tid] = 0.f; s_same[tid] = 0.f; s_S[tid] = 0.f; s_mx[tid] = 0u;
        c_full[tid] = 0.f; c_same[tid] = 0.f; c_S[tid] = 0.f; c_mx[tid] = 0u;
    }

    const float* Asrc = (rowbase < NH) ? f1 + (size_t)rowbase * FD
                                       : f2 + (size_t)(rowbase - NH) * FD;
    const float* Bsrc = (colbase < NH) ? f1 + (size_t)colbase * FD
                                       : f2 + (size_t)(colbase - NH) * FD;

    #pragma unroll
    for (int it = 0; it < 16; ++it) {
        int idx = it * 256 + tid;
        int row = idx >> 5, kq = (idx & 31) << 2;
        unsigned so = swz(row, kq);
        uint2 hi, lo;
        cvt_hilo(*(const float4*)(Asrc + row * FD + kq), hi, lo);
        *(uint2*)(smc + SM_AHI + so) = hi;
        *(uint2*)(smc + SM_ALO + so) = lo;
        float4 vb = *(const float4*)(Bsrc + row * FD + kq);
        __nv_bfloat162 b01 = __floats2bfloat162_rn(vb.x, vb.y);
        __nv_bfloat162 b23 = __floats2bfloat162_rn(vb.z, vb.w);
        *(uint2*)(smc + SM_B + so) = make_uint2(*(unsigned*)&b01, *(unsigned*)&b23);
    }
    __syncthreads();

    const int rA  = ((lane >> 3) & 1) * 8 + (lane & 7);
    const int kbA = (lane >> 4) & 1;
    const int rB  = ((lane >> 4) & 1) * 8 + (lane & 7);
    const int kbB = (lane >> 3) & 1;
    const unsigned roA = (unsigned)(m0 + rA) * 256u;
    const unsigned roB = (unsigned)(n0 + rB) * 256u;

    float acc[4][4][4];
    #pragma unroll
    for (int mi = 0; mi < 4; mi++)
        #pragma unroll
        for (int ni = 0; ni < 4; ni++)
            #pragma unroll
            for (int u = 0; u < 4; u++) acc[mi][ni][u] = 0.f;

    // Fused passes 1+2: (Ahi + Alo) * Bhi.
    #pragma unroll 2
    for (int ks = 0; ks < 8; ++ks) {
        unsigned chA = ((unsigned)((ks * 2 + kbA) ^ (rA & 7))) << 4;
        unsigned chB = ((unsigned)((ks * 2 + kbB) ^ (rB & 7))) << 4;
        unsigned bF[2][4];
        #pragma unroll
        for (int nj = 0; nj < 2; nj++)
            LDSM4(bF[nj], sbase + SM_B + roB + (unsigned)(nj * 16) * 256u + chB);
        #pragma unroll
        for (int mi = 0; mi < 4; mi++) {
            unsigned aH[4], aL[4];
            LDSM4(aH, sbase + SM_AHI + roA + (unsigned)(mi * 16) * 256u + chA);
            LDSM4(aL, sbase + SM_ALO + roA + (unsigned)(mi * 16) * 256u + chA);
            #pragma unroll
            for (int ni = 0; ni < 4; ni++) {
                int p = ni >> 1, s = (ni & 1) * 2;
                MMA(acc[mi][ni], aH, bF[p][s], bF[p][s + 1]);
                MMA(acc[mi][ni], aL, bF[p][s], bF[p][s + 1]);
            }
        }
    }

    // Pair-scoped: both warps of pair {w, w+4} done reading B-hi slice.
    PAIR_BAR(pairid);

    // Per-pair B-lo reload: 64 threads convert rows [n0, n0+32) only.
    {
        const int pt = ((wid >> 2) << 5) + lane;        // 0..63 within pair
        #pragma unroll
        for (int it = 0; it < 16; ++it) {
            int idx = it * 64 + pt;                     // 1024 float4 slots
            int rloc = n0 + (idx >> 5);
            int kq = (idx & 31) << 2;
            uint2 hi, lo;
            cvt_hilo(*(const float4*)(Bsrc + rloc * FD + kq), hi, lo);
            *(uint2*)(smc + SM_B + swz(rloc, kq)) = lo;
        }
    }
    PAIR_BAR(pairid);

    // Pass 3: Ahi * Blo
    #pragma unroll 2
    for (int ks = 0; ks < 8; ++ks) {
        unsigned chA = ((unsigned)((ks * 2 + kbA) ^ (rA & 7))) << 4;
        unsigned chB = ((unsigned)((ks * 2 + kbB) ^ (rB & 7))) << 4;
        unsigned bF[2][4];
        #pragma unroll
        for (int nj = 0; nj < 2; nj++)
            LDSM4(bF[nj], sbase + SM_B + roB + (unsigned)(nj * 16) * 256u + chB);
        #pragma unroll
        for (int mi = 0; mi < 4; mi++) {
            unsigned aH[4];
            LDSM4(aH, sbase + SM_AHI + roA + (unsigned)(mi * 16) * 256u + chA);
            #pragma unroll
            for (int ni = 0; ni < 4; ni++) {
                int p = ni >> 1, s = (ni & 1) * 2;
                MMA(acc[mi][ni], aH, bF[p][s], bF[p][s + 1]);
            }
        }
    }

    // ---------------- epilogue ----------------
    const bool is2i = rowbase >= NH, is2j = colbase >= NH;
    const float wgt = (is2i != is2j) ? 0.5f : 1.0f;
    const int grp = lane >> 2, t4 = lane & 3;

    int labi[8];
    #pragma unroll
    for (int rj = 0; rj < 8; rj++)
        labi[rj] = (unsigned char)smc[SM_LABR + m0 + (rj >> 1) * 16 + grp + (rj & 1) * 8];

    if (diag) {
        #pragma unroll
        for (int rj = 0; rj < 8; rj++) {
            int mi = rj >> 1, h = rj & 1;
            int rloc = m0 + mi * 16 + grp + h * 8;
            int grow = rowbase + rloc;
            float full = 0.f, sme = 0.f, Sa = 0.f, mx = -1e30f;
            #pragma unroll
            for (int ni = 0; ni < 4; ni++) {
                #pragma unroll
                for (int u = 0; u < 2; u++) {
                    float x = acc[mi][ni][h * 2 + u] * TEMPC;
                    float e = fast_exp(x);
                    full += e;
                    int cloc = n0 + ni * 8 + t4 * 2 + u;
                    int lq = (unsigned char)smc[SM_LABC + cloc];
                    if (lq == labi[rj]) {
                        sme += e;
                        Sa = fmaf(wgt, x, Sa);
                        int j = colbase + cloc;
                        int pidx = (j & 63) + ((is2j && labi[rj] < KCLS) ? 64 : 0);
                        g_pos[grow][pidx] = x;
                    } else {
                        mx = fmaxf(mx, x);
                    }
                }
            }
            #pragma unroll
            for (int o = 1; o < 4; o <<= 1) {
                full += __shfl_xor_sync(0xffffffffu, full, o);
                sme  += __shfl_xor_sync(0xffffffffu, sme,  o);
                Sa   += __shfl_xor_sync(0xffffffffu, Sa,   o);
                mx = fmaxf(mx, __shfl_xor_sync(0xffffffffu, mx, o));
            }
            if (t4 == 0) {
                atomicAdd(&s_full[rloc], full);
                atomicAdd(&s_same[rloc], sme);
                atomicAdd(&s_S[rloc], Sa);
                atomicMax(&s_mx[rloc], encf(mx));
            }
        }
    } else {
        float rfull[8], rsme[8], rS[8], rmx[8];
        #pragma unroll
        for (int rj = 0; rj < 8; rj++) {
            rfull[rj] = 0.f; rsme[rj] = 0.f; rS[rj] = 0.f; rmx[rj] = -1e30f;
        }

        #pragma unroll
        for (int ni = 0; ni < 4; ni++) {
            float cf[2] = {0.f, 0.f}, cs[2] = {0.f, 0.f}, cS2[2] = {0.f, 0.f};
            float cm[2] = {-1e30f, -1e30f};
            int lq[2], cloc[2];
            #pragma unroll
            for (int u = 0; u < 2; u++) {
                cloc[u] = n0 + ni * 8 + t4 * 2 + u;
                lq[u] = (unsigned char)smc[SM_LABC + cloc[u]];
            }
            #pragma unroll
            for (int rj = 0; rj < 8; rj++) {
                int mi = rj >> 1, h = rj & 1;
                int rloc = m0 + mi * 16 + grp + h * 8;
                int grow = rowbase + rloc;
                int pidx2 = (grow & 63) + ((is2i && labi[rj] < KCLS) ? 64 : 0);
                #pragma unroll
                for (int u = 0; u < 2; u++) {
                    float x = acc[mi][ni][h * 2 + u] * TEMPC;
                    float e = fast_exp(x);
                    rfull[rj] += e;
                    cf[u] += e;
                    if (lq[u] == labi[rj]) {
                        rsme[rj] += e;
                        rS[rj] = fmaf(wgt, x, rS[rj]);
                        cs[u] += e;
                        cS2[u] = fmaf(wgt, x, cS2[u]);
                        int j = colbase + cloc[u];
                        int pidx = (j & 63) + ((is2j && labi[rj] < KCLS) ? 64 : 0);
                        g_pos[grow][pidx] = x;
                        g_pos[j][pidx2] = x;
                    } else {
                        rmx[rj] = fmaxf(rmx[rj], x);
                        cm[u] = fmaxf(cm[u], x);
                    }
                }
            }
            #pragma unroll
            for (int u = 0; u < 2; u++) {
                #pragma unroll
                for (int o = 4; o < 32; o <<= 1) {
                    cf[u]  += __shfl_xor_sync(0xffffffffu, cf[u],  o);
                    cs[u]  += __shfl_xor_sync(0xffffffffu, cs[u],  o);
                    cS2[u] += __shfl_xor_sync(0xffffffffu, cS2[u], o);
                    cm[u] = fmaxf(cm[u], __shfl_xor_sync(0xffffffffu, cm[u], o));
                }
                if (grp == 0) {
                    atomicAdd(&c_full[cloc[u]], cf[u]);
                    atomicAdd(&c_same[cloc[u]], cs[u]);
                    atomicAdd(&c_S[cloc[u]], cS2[u]);
                    atomicMax(&c_mx[cloc[u]], encf(cm[u]));
                }
            }
        }

        #pragma unroll
        for (int rj = 0; rj < 8; rj++) {
            int rloc = m0 + (rj >> 1) * 16 + grp + (rj & 1) * 8;
            float full = rfull[rj], sme = rsme[rj], Sa = rS[rj], mx = rmx[rj];
            #pragma unroll
            for (int o = 1; o < 4; o <<= 1) {
                full += __shfl_xor_sync(0xffffffffu, full, o);
                sme  += __shfl_xor_sync(0xffffffffu, sme,  o);
                Sa   += __shfl_xor_sync(0xffffffffu, Sa,   o);
                mx = fmaxf(mx, __shfl_xor_sync(0xffffffffu, mx, o));
            }
            if (t4 == 0) {
                atomicAdd(&s_full[rloc], full);
                atomicAdd(&s_same[rloc], sme);
                atomicAdd(&s_S[rloc], Sa);
                atomicMax(&s_mx[rloc], encf(mx));
            }
        }
    }

    __syncthreads();
    if (tid < 128) {
        g_part[rowbase + tid][bx] = make_float4(s_full[tid], s_same[tid], s_S[tid],
                                                __uint_as_float(s_mx[tid]));
        if (!diag)
            g_part[colbase + tid][by] = make_float4(c_full[tid], c_same[tid], c_S[tid],
                                                    __uint_as_float(c_mx[tid]));
    }

    // ---------------- fused band reduction ----------------
    __syncthreads();
    if (tid == 0) {
        __threadfence();
        int n = 0;
        if (atomicAdd(&g_cnt[by], 1u) == 31u) s_todo[n++] = by;
        if (bx != by && atomicAdd(&g_cnt[bx], 1u) == 31u) s_todo[n++] = bx;
        s_nt = n;
    }
    __syncthreads();
    const int ntodo = s_nt;

    for (int t = 0; t < ntodo; t++) {
        const int band = s_todo[t];
        __threadfence();   // acquire: all 32 writers' data visible

        float lossA = 0.f; int corrA = 0, npA = 0;
        for (int rr = 0; rr < 16; rr++) {
            int row = (band << 7) + (wid << 4) + rr;
            float4 p = g_part[row][lane];
            float fu = p.x, sm2 = p.y, Ss = p.z;
            unsigned mxe = __float_as_uint(p.w);
            #pragma unroll
            for (int o = 16; o > 0; o >>= 1) {
                fu  += __shfl_xor_sync(0xffffffffu, fu,  o);
                sm2 += __shfl_xor_sync(0xffffffffu, sm2, o);
                Ss  += __shfl_xor_sync(0xffffffffu, Ss,  o);
                mxe = max(mxe, __shfl_xor_sync(0xffffffffu, mxe, o));
            }
            int L = labelOf(row, ovm);
            bool ovl = (L < KCLS) && ((ovm >> L) & 1u);
            int cnt2 = ovl ? 128 : 64;
            int selfidx = (row & 63) + ((row >= NH && L < KCLS) ? 64 : 0);
            float mn = decf(mxe);
            #pragma unroll
            for (int k2 = 0; k2 < 4; k2++) {
                int t2 = lane + (k2 << 5);
                if (t2 < cnt2 && t2 != selfidx && g_pos[row][t2] > mn) corrA++;
            }
            if (lane == 0) {
                float xself = g_pos[row][selfidx];
                float W = ovl ? 95.0f : 63.0f;
                lossA += fmaf(W, logf(fu - sm2), -(Ss - xself));
                npA += cnt2 - 1;
            }
        }
        #pragma unroll
        for (int o = 16; o > 0; o >>= 1)
            corrA += __shfl_xor_sync(0xffffffffu, corrA, o);

        if (lane == 0) { r_l[wid] = lossA; r_c[wid] = corrA; r_n[wid] = npA; }
        __syncthreads();
        if (tid == 0) {
            float lt = 0.f; int ct = 0, nt2 = 0;
            #pragma unroll
            for (int i = 0; i < 8; i++) { lt += r_l[i]; ct += r_c[i]; nt2 += r_n[i]; }
            atomicAdd(&g_loss, lt);
            atomicAdd(&g_corr, ct);
            atomicAdd(&g_np, nt2);
            g_cnt[band] = 0u;              // self-clean for next replay
            __threadfence();
            if (atomicAdd(&g_bdone, 1u) == 31u) {
                __threadfence();
                float npf = (float)g_np;
                if (out_size >= 1) out[0] = (float)g_corr / npf;
                if (out_size >= 2) out[1] = g_loss / npf;
                g_loss = 0.f; g_corr = 0; g_np = 0; g_bdone = 0u;  // self-clean
            }
        }
        __syncthreads();   // r_* reused if second band
    }
}

extern "C" void kernel_launch(void* const* d_in, const int* in_sizes, int n_in,
                              void* d_out, int out_size) {
    const float* f1 = nullptr;
    const float* f2 = nullptr;
    const unsigned char* ov = nullptr;
    for (int i = 0; i < n_in; i++) {
        if (in_sizes[i] == NH * FD) {
            if (!f1) f1 = (const float*)d_in[i];
            else if (!f2) f2 = (const float*)d_in[i];
        } else if (in_sizes[i] == KCLS) {
            ov = (const unsigned char*)d_in[i];
        }
    }
    cudaFuncSetAttribute(k_main, cudaFuncAttributeMaxDynamicSharedMemorySize, SM_TOTAL);

    k_main<<<528, 256, SM_TOTAL>>>(f1, f2, ov, (float*)d_out, out_size);
}

// round 16
// speedup vs baseline: 1.5047x; 1.5047x over previous
#include <cuda_runtime.h>
#include <cuda_bf16.h>

// ContrastiveLoss on GB300 — symmetric-triangular 3-pass bf16-split HMMA GEMM.
// R16: revert of the R15 fusion (regressed 49.3->71.6: extra live state past
// the 128-reg cap spilled into the hot loops). Back to the R14 two-kernel
// structure + two latency fixes:
//   (1) global-load phases batched 4 float4s deep (MLP 2 -> 8) in both the
//       initial A/B load and the per-pair B-lo reload;
//   (2) k_rows accuracy loads hoisted above the shuffle-reduce dependency.
// Pad kernel dropped (speed > capture alignment this round).
//
//   k_main : 528 tiles (off-diag first, diag last). 3-pass exact bf16 split;
//            pair-scoped barriers around per-pair B-lo reload; fused epilogue;
//            MUFU ex2; row+col stats -> float4 partials g_part[row][colblock];
//            g_pos scatter both directions.
//   k_rows : one warp per row; coalesced partial reads; accuracy scan; out[].

#define NTOT 4096
#define NH   2048
#define FD   128
#define KCLS 32
#define TEMPC 0.01f

__device__ float4        g_part[NTOT][32];   // x=full y=same z=S w=mxenc(bits)
__device__ float         g_pos[NTOT][128];
__device__ float         g_loss;
__device__ int           g_corr;
__device__ int           g_np;
__device__ unsigned int  g_done;

__device__ __forceinline__ unsigned int encf(float f) {
    unsigned int u = __float_as_uint(f);
    return (u & 0x80000000u) ? ~u : (u | 0x80000000u);
}
__device__ __forceinline__ float decf(unsigned int v) {
    unsigned int u = (v & 0x80000000u) ? (v & 0x7FFFFFFFu) : ~v;
    return __uint_as_float(u);
}

__device__ unsigned sniff_ov(const unsigned char* __restrict__ ovraw) {
    const unsigned* u32p = (const unsigned*)ovraw;
    bool allF = true, anyF = false;
    #pragma unroll
    for (int c = 0; c < 8; c++) {
        unsigned u = u32p[c];
        if (u != 0u && u != 0x3F800000u) allF = false;
        if (u == 0x3F800000u) anyF = true;
    }
    int mode;
    if (allF && anyF) mode = 2;
    else {
        bool oddNZ = false;
        for (int i = 0; i < 32; i++) if ((i & 3) && ovraw[i]) oddNZ = true;
        mode = oddNZ ? 0 : 1;
    }
    unsigned m = 0;
    for (int c = 0; c < 32; c++) {
        bool ov;
        if (mode == 0)      ov = ovraw[c] != 0;
        else if (mode == 1) ov = ((const int*)ovraw)[c] != 0;
        else                ov = ((const float*)ovraw)[c] != 0.f;
        m |= (ov ? 1u : 0u) << c;
    }
    return m;
}

__device__ __forceinline__ int labelOf(int i, unsigned ovm) {
    if (i < NH) return i >> 6;
    int c = (i - NH) >> 6;
    if ((ovm >> c) & 1u) return c;
    return KCLS + __popc((~ovm) & ((1u << c) - 1u));
}

// ---------------- helpers ----------------

__device__ __forceinline__ unsigned smem_u32(const void* p) {
    unsigned a;
    asm("{ .reg .u64 t; cvta.to.shared.u64 t, %1; cvt.u32.u64 %0, t; }"
        : "=r"(a) : "l"(p));
    return a;
}

#define LDSM4(r, a) \
    asm volatile("ldmatrix.sync.aligned.m8n8.x4.shared.b16 {%0,%1,%2,%3}, [%4];" \
        : "=r"((r)[0]), "=r"((r)[1]), "=r"((r)[2]), "=r"((r)[3]) : "r"(a))

#define MMA(c, a, b0, b1) \
    asm volatile("mma.sync.aligned.m16n8k16.row.col.f32.bf16.bf16.f32 " \
        "{%0,%1,%2,%3}, {%4,%5,%6,%7}, {%8,%9}, {%0,%1,%2,%3};" \
        : "+f"((c)[0]), "+f"((c)[1]), "+f"((c)[2]), "+f"((c)[3]) \
        : "r"((a)[0]), "r"((a)[1]), "r"((a)[2]), "r"((a)[3]), "r"(b0), "r"(b1))

// Pair-scoped barrier: warps w and w+4 (same n0 / same B slice), 64 threads.
#define PAIR_BAR(pairid) \
    asm volatile("bar.sync %0, 64;" :: "r"(1 + (pairid)) : "memory")

__device__ __forceinline__ unsigned pack2(float a, float b) {
    __nv_bfloat162 t = __floats2bfloat162_rn(a, b);
    return *(unsigned*)&t;
}

__device__ __forceinline__ unsigned swz(int row, int kq) {
    return (unsigned)row * 256u
         + ((((unsigned)(kq >> 3)) ^ ((unsigned)row & 7u)) << 4)
         + (((unsigned)kq & 7u) << 1);
}

__device__ __forceinline__ void cvt_hilo(float4 v, uint2& hi, uint2& lo) {
    __nv_bfloat16 h0 = __float2bfloat16(v.x);
    __nv_bfloat16 h1 = __float2bfloat16(v.y);
    __nv_bfloat16 h2 = __float2bfloat16(v.z);
    __nv_bfloat16 h3 = __float2bfloat16(v.w);
    __nv_bfloat162 t01; t01.x = h0; t01.y = h1;
    __nv_bfloat162 t23; t23.x = h2; t23.y = h3;
    hi = make_uint2(*(unsigned*)&t01, *(unsigned*)&t23);
    lo = make_uint2(pack2(v.x - __bfloat162float(h0), v.y - __bfloat162float(h1)),
                    pack2(v.z - __bfloat162float(h2), v.w - __bfloat162float(h3)));
}

// MUFU-based exp: comparisons use raw x; approx only perturbs sums ~1e-6.
__device__ __forceinline__ float fast_exp(float x) {
    float r;
    asm("ex2.approx.ftz.f32 %0, %1;" : "=f"(r) : "f"(x * 1.44269504f));
    return r;
}

// ---------------- main kernel ----------------

#define SM_AHI  0
#define SM_ALO  32768
#define SM_B    65536
#define SM_LABC 98304
#define SM_LABR 98432
#define SM_RED  98560                   // row arrays: 4 x 512B
#define SM_RED2 (98560 + 2048)          // col arrays: 4 x 512B
#define SM_TOTAL (98560 + 4096)

__global__ void __launch_bounds__(256, 2)
k_main(const float* __restrict__ f1, const float* __restrict__ f2,
       const unsigned char* __restrict__ ovraw) {
    // Decode: indices [0,496) = strict-upper off-diag pairs, [496,528) = diag.
    int bx, by;
    if (blockIdx.x >= 496) {
        by = blockIdx.x - 496; bx = by;
    } else {
        int tt0 = blockIdx.x; by = 0;
        while (tt0 >= 31 - by) { tt0 -= 31 - by; by++; }
        bx = by + 1 + tt0;
    }
    const bool diag = (bx == by);

    extern __shared__ char smc[];
    unsigned sbase = smem_u32(smc);
    float* s_full = (float*)(smc + SM_RED);
    float* s_same = s_full + 128;
    float* s_S    = s_same + 128;
    unsigned* s_mx = (unsigned*)(s_S + 128);
    float* c_full = (float*)(smc + SM_RED2);
    float* c_same = c_full + 128;
    float* c_S    = c_same + 128;
    unsigned* c_mx = (unsigned*)(c_S + 128);
    __shared__ unsigned s_ovm;

    const int tid = threadIdx.x, wid = tid >> 5, lane = tid & 31;
    const int rowbase = by << 7, colbase = bx << 7;
    const int m0 = (wid >> 2) << 6;
    const int n0 = (wid & 3) << 5;
    const int pairid = wid & 3;

    if (tid == 0) {
        s_ovm = sniff_ov(ovraw);
        if (blockIdx.x == 0) { g_loss = 0.f; g_corr = 0; g_np = 0; g_done = 0u; }
    }
    __syncthreads();
    const unsigned ovm = s_ovm;

    if (tid < 128) {
        smc[SM_LABC + tid] = (char)labelOf(colbase + tid, ovm);
        smc[SM_LABR + tid] = (char)labelOf(rowbase + tid, ovm);
        s_full[tid] = 0.f; s_same[tid] = 0.f; s_S[tid] = 0.f; s_mx[tid] = 0u;
        c_full[tid] = 0.f; c_same[tid] = 0.f; c_S[tid] = 0.f; c_mx[tid] = 0u;
    }

    const float* Asrc = (rowbase < NH) ? f1 + (size_t)rowbase * FD
                                       : f2 + (size_t)(rowbase - NH) * FD;
    const float* Bsrc = (colbase < NH) ? f1 + (size_t)colbase * FD
                                       : f2 + (size_t)(colbase - NH) * FD;

    // Batched load phase: 4 chunks x (4 A-float4 + 4 B-float4 outstanding).
    #pragma unroll
    for (int c = 0; c < 4; ++c) {
        float4 va[4], vb[4];
        int row[4], kq[4];
        #pragma unroll
        for (int j = 0; j < 4; ++j) {
            int idx = (c * 4 + j) * 256 + tid;
            row[j] = idx >> 5; kq[j] = (idx & 31) << 2;
            va[j] = *(const float4*)(Asrc + row[j] * FD + kq[j]);
            vb[j] = *(const float4*)(Bsrc + row[j] * FD + kq[j]);
        }
        #pragma unroll
        for (int j = 0; j < 4; ++j) {
            unsigned so = swz(row[j], kq[j]);
            uint2 hi, lo;
            cvt_hilo(va[j], hi, lo);
            *(uint2*)(smc + SM_AHI + so) = hi;
            *(uint2*)(smc + SM_ALO + so) = lo;
            __nv_bfloat162 b01 = __floats2bfloat162_rn(vb[j].x, vb[j].y);
            __nv_bfloat162 b23 = __floats2bfloat162_rn(vb[j].z, vb[j].w);
            *(uint2*)(smc + SM_B + so) = make_uint2(*(unsigned*)&b01, *(unsigned*)&b23);
        }
    }
    __syncthreads();

    const int rA  = ((lane >> 3) & 1) * 8 + (lane & 7);
    const int kbA = (lane >> 4) & 1;
    const int rB  = ((lane >> 4) & 1) * 8 + (lane & 7);
    const int kbB = (lane >> 3) & 1;
    const unsigned roA = (unsigned)(m0 + rA) * 256u;
    const unsigned roB = (unsigned)(n0 + rB) * 256u;

    float acc[4][4][4];
    #pragma unroll
    for (int mi = 0; mi < 4; mi++)
        #pragma unroll
        for (int ni = 0; ni < 4; ni++)
            #pragma unroll
            for (int u = 0; u < 4; u++) acc[mi][ni][u] = 0.f;

    // Fused passes 1+2: (Ahi + Alo) * Bhi.
    #pragma unroll 2
    for (int ks = 0; ks < 8; ++ks) {
        unsigned chA = ((unsigned)((ks * 2 + kbA) ^ (rA & 7))) << 4;
        unsigned chB = ((unsigned)((ks * 2 + kbB) ^ (rB & 7))) << 4;
        unsigned bF[2][4];
        #pragma unroll
        for (int nj = 0; nj < 2; nj++)
            LDSM4(bF[nj], sbase + SM_B + roB + (unsigned)(nj * 16) * 256u + chB);
        #pragma unroll
        for (int mi = 0; mi < 4; mi++) {
            unsigned aH[4], aL[4];
            LDSM4(aH, sbase + SM_AHI + roA + (unsigned)(mi * 16) * 256u + chA);
            LDSM4(aL, sbase + SM_ALO + roA + (unsigned)(mi * 16) * 256u + chA);
            #pragma unroll
            for (int ni = 0; ni < 4; ni++) {
                int p = ni >> 1, s = (ni & 1) * 2;
                MMA(acc[mi][ni], aH, bF[p][s], bF[p][s + 1]);
                MMA(acc[mi][ni], aL, bF[p][s], bF[p][s + 1]);
            }
        }
    }

    // Pair-scoped: both warps of pair {w, w+4} done reading B-hi slice.
    PAIR_BAR(pairid);

    // Per-pair B-lo reload, batched 4 deep: rows [n0, n0+32) only.
    {
        const int pt = ((wid >> 2) << 5) + lane;        // 0..63 within pair
        #pragma unroll
        for (int c = 0; c < 4; ++c) {
            float4 vb[4];
            int rloc[4], kq[4];
            #pragma unroll
            for (int j = 0; j < 4; ++j) {
                int idx = (c * 4 + j) * 64 + pt;        // 1024 float4 slots
                rloc[j] = n0 + (idx >> 5);
                kq[j] = (idx & 31) << 2;
                vb[j] = *(const float4*)(Bsrc + rloc[j] * FD + kq[j]);
            }
            #pragma unroll
            for (int j = 0; j < 4; ++j) {
                uint2 hi, lo;
                cvt_hilo(vb[j], hi, lo);
                *(uint2*)(smc + SM_B + swz(rloc[j], kq[j])) = lo;
            }
        }
    }
    PAIR_BAR(pairid);

    // Pass 3: Ahi * Blo
    #pragma unroll 2
    for (int ks = 0; ks < 8; ++ks) {
        unsigned chA = ((unsigned)((ks * 2 + kbA) ^ (rA & 7))) << 4;
        unsigned chB = ((unsigned)((ks * 2 + kbB) ^ (rB & 7))) << 4;
        unsigned bF[2][4];
        #pragma unroll
        for (int nj = 0; nj < 2; nj++)
            LDSM4(bF[nj], sbase + SM_B + roB + (unsigned)(nj * 16) * 256u + chB);
        #pragma unroll
        for (int mi = 0; mi < 4; mi++) {
            unsigned aH[4];
            LDSM4(aH, sbase + SM_AHI + roA + (unsigned)(mi * 16) * 256u + chA);
            #pragma unroll
            for (int ni = 0; ni < 4; ni++) {
                int p = ni >> 1, s = (ni & 1) * 2;
                MMA(acc[mi][ni], aH, bF[p][s], bF[p][s + 1]);
            }
        }
    }

    // ---------------- epilogue ----------------
    const bool is2i = rowbase >= NH, is2j = colbase >= NH;
    const float wgt = (is2i != is2j) ? 0.5f : 1.0f;
    const int grp = lane >> 2, t4 = lane & 3;

    int labi[8];
    #pragma unroll
    for (int rj = 0; rj < 8; rj++)
        labi[rj] = (unsigned char)smc[SM_LABR + m0 + (rj >> 1) * 16 + grp + (rj & 1) * 8];

    if (diag) {
        #pragma unroll
        for (int rj = 0; rj < 8; rj++) {
            int mi = rj >> 1, h = rj & 1;
            int rloc = m0 + mi * 16 + grp + h * 8;
            int grow = rowbase + rloc;
            float full = 0.f, sme = 0.f, Sa = 0.f, mx = -1e30f;
            #pragma unroll
            for (int ni = 0; ni < 4; ni++) {
                #pragma unroll
                for (int u = 0; u < 2; u++) {
                    float x = acc[mi][ni][h * 2 + u] * TEMPC;
                    float e = fast_exp(x);
                    full += e;
                    int cloc = n0 + ni * 8 + t4 * 2 + u;
                    int lq = (unsigned char)smc[SM_LABC + cloc];
                    if (lq == labi[rj]) {
                        sme += e;
                        Sa = fmaf(wgt, x, Sa);
                        int j = colbase + cloc;
                        int pidx = (j & 63) + ((is2j && labi[rj] < KCLS) ? 64 : 0);
                        g_pos[grow][pidx] = x;
                    } else {
                        mx = fmaxf(mx, x);
                    }
                }
            }
            #pragma unroll
            for (int o = 1; o < 4; o <<= 1) {
                full += __shfl_xor_sync(0xffffffffu, full, o);
                sme  += __shfl_xor_sync(0xffffffffu, sme,  o);
                Sa   += __shfl_xor_sync(0xffffffffu, Sa,   o);
                mx = fmaxf(mx, __shfl_xor_sync(0xffffffffu, mx, o));
            }
            if (t4 == 0) {
                atomicAdd(&s_full[rloc], full);
                atomicAdd(&s_same[rloc], sme);
                atomicAdd(&s_S[rloc], Sa);
                atomicMax(&s_mx[rloc], encf(mx));
            }
        }
    } else {
        float rfull[8], rsme[8], rS[8], rmx[8];
        #pragma unroll
        for (int rj = 0; rj < 8; rj++) {
            rfull[rj] = 0.f; rsme[rj] = 0.f; rS[rj] = 0.f; rmx[rj] = -1e30f;
        }

        #pragma unroll
        for (int ni = 0; ni < 4; ni++) {
            float cf[2] = {0.f, 0.f}, cs[2] = {0.f, 0.f}, cS2[2] = {0.f, 0.f};
            float cm[2] = {-1e30f, -1e30f};
            int lq[2], cloc[2];
            #pragma unroll
            for (int u = 0; u < 2; u++) {
                cloc[u] = n0 + ni * 8 + t4 * 2 + u;
                lq[u] = (unsigned char)smc[SM_LABC + cloc[u]];
            }
            #pragma unroll
            for (int rj = 0; rj < 8; rj++) {
                int mi = rj >> 1, h = rj & 1;
                int rloc = m0 + mi * 16 + grp + h * 8;
                int grow = rowbase + rloc;
                int pidx2 = (grow & 63) + ((is2i && labi[rj] < KCLS) ? 64 : 0);
                #pragma unroll
                for (int u = 0; u < 2; u++) {
                    float x = acc[mi][ni][h * 2 + u] * TEMPC;
                    float e = fast_exp(x);
                    rfull[rj] += e;
                    cf[u] += e;
                    if (lq[u] == labi[rj]) {
                        rsme[rj] += e;
                        rS[rj] = fmaf(wgt, x, rS[rj]);
                        cs[u] += e;
                        cS2[u] = fmaf(wgt, x, cS2[u]);
                        int j = colbase + cloc[u];
                        int pidx = (j & 63) + ((is2j && labi[rj] < KCLS) ? 64 : 0);
                        g_pos[grow][pidx] = x;
                        g_pos[j][pidx2] = x;
                    } else {
                        rmx[rj] = fmaxf(rmx[rj], x);
                        cm[u] = fmaxf(cm[u], x);
                    }
                }
            }
            #pragma unroll
            for (int u = 0; u < 2; u++) {
                #pragma unroll
                for (int o = 4; o < 32; o <<= 1) {
                    cf[u]  += __shfl_xor_sync(0xffffffffu, cf[u],  o);
                    cs[u]  += __shfl_xor_sync(0xffffffffu, cs[u],  o);
                    cS2[u] += __shfl_xor_sync(0xffffffffu, cS2[u], o);
                    cm[u] = fmaxf(cm[u], __shfl_xor_sync(0xffffffffu, cm[u], o));
                }
                if (grp == 0) {
                    atomicAdd(&c_full[cloc[u]], cf[u]);
                    atomicAdd(&c_same[cloc[u]], cs[u]);
                    atomicAdd(&c_S[cloc[u]], cS2[u]);
                    atomicMax(&c_mx[cloc[u]], encf(cm[u]));
                }
            }
        }

        #pragma unroll
        for (int rj = 0; rj < 8; rj++) {
            int rloc = m0 + (rj >> 1) * 16 + grp + (rj & 1) * 8;
            float full = rfull[rj], sme = rsme[rj], Sa = rS[rj], mx = rmx[rj];
            #pragma unroll
            for (int o = 1; o < 4; o <<= 1) {
                full += __shfl_xor_sync(0xffffffffu, full, o);
                sme  += __shfl_xor_sync(0xffffffffu, sme,  o);
                Sa   += __shfl_xor_sync(0xffffffffu, Sa,   o);
                mx = fmaxf(mx, __shfl_xor_sync(0xffffffffu, mx, o));
            }
            if (t4 == 0) {
                atomicAdd(&s_full[rloc], full);
                atomicAdd(&s_same[rloc], sme);
                atomicAdd(&s_S[rloc], Sa);
                atomicMax(&s_mx[rloc], encf(mx));
            }
        }
    }

    __syncthreads();
    if (tid < 128) {
        g_part[rowbase + tid][bx] = make_float4(s_full[tid], s_same[tid], s_S[tid],
                                                __uint_as_float(s_mx[tid]));
        if (!diag)
            g_part[colbase + tid][by] = make_float4(c_full[tid], c_same[tid], c_S[tid],
                                                    __uint_as_float(c_mx[tid]));
    }
}

// ---------------- reduction kernel: one warp per row ----------------

__global__ void __launch_bounds__(256)
k_rows(const unsigned char* __restrict__ ovraw, float* out, int out_size) {
    __shared__ unsigned s_ovm;
    __shared__ float s_l[8];
    __shared__ int   s_c[8];
    __shared__ int   s_n[8];
    const int tid = threadIdx.x, lane = tid & 31, w = tid >> 5;
    if (tid == 0) s_ovm = sniff_ov(ovraw);
    __syncthreads();
    const unsigned ovm = s_ovm;
    const int row = blockIdx.x * 8 + w;

    // Issue ALL loads up front (independent of the reduce chain).
    float4 p = g_part[row][lane];
    float v[4];
    #pragma unroll
    for (int k2 = 0; k2 < 4; k2++)
        v[k2] = g_pos[row][lane + (k2 << 5)];   // always in-bounds

    float full = p.x, sme = p.y, S = p.z;
    unsigned mxe = __float_as_uint(p.w);
    #pragma unroll
    for (int o = 16; o > 0; o >>= 1) {
        full += __shfl_xor_sync(0xffffffffu, full, o);
        sme  += __shfl_xor_sync(0xffffffffu, sme,  o);
        S    += __shfl_xor_sync(0xffffffffu, S,    o);
        mxe = max(mxe, __shfl_xor_sync(0xffffffffu, mxe, o));
    }

    const int L = labelOf(row, ovm);
    const bool ovl = (L < KCLS) ? ((ovm >> L) & 1u) : false;
    const int cnt = ovl ? 128 : 64;
    const int selfidx = (row & 63) + ((row >= NH && L < KCLS) ? 64 : 0);
    const float mn = decf(mxe);

    int corr = 0;
    #pragma unroll
    for (int k2 = 0; k2 < 4; k2++) {
        int t2 = lane + (k2 << 5);
        if (t2 < cnt && t2 != selfidx && v[k2] > mn) corr++;
    }
    #pragma unroll
    for (int o = 16; o > 0; o >>= 1)
        corr += __shfl_xor_sync(0xffffffffu, corr, o);

    if (lane == 0) {
        float xself = g_pos[row][selfidx];
        float W = ovl ? 95.0f : 63.0f;
        s_l[w] = fmaf(W, logf(full - sme), -(S - xself));
        s_c[w] = corr;
        s_n[w] = cnt - 1;
    }
    __syncthreads();
    if (tid == 0) {
        float lt = 0.f; int ct = 0, nt = 0;
        #pragma unroll
        for (int i = 0; i < 8; i++) { lt += s_l[i]; ct += s_c[i]; nt += s_n[i]; }
        atomicAdd(&g_loss, lt);
        atomicAdd(&g_corr, ct);
        atomicAdd(&g_np, nt);
        __threadfence();
        unsigned d = atomicAdd(&g_done, 1u);
        if (d == gridDim.x - 1) {
            __threadfence();
            float npf = (float)g_np;
            if (out_size >= 1) out[0] = (float)g_corr / npf;
            if (out_size >= 2) out[1] = g_loss / npf;
        }
    }
}

extern "C" void kernel_launch(void* const* d_in, const int* in_sizes, int n_in,
                              void* d_out, int out_size) {
    const float* f1 = nullptr;
    const float* f2 = nullptr;
    const unsigned char* ov = nullptr;
    for (int i = 0; i < n_in; i++) {
        if (in_sizes[i] == NH * FD) {
            if (!f1) f1 = (const float*)d_in[i];
            else if (!f2) f2 = (const float*)d_in[i];
        } else if (in_sizes[i] == KCLS) {
            ov = (const unsigned char*)d_in[i];
        }
    }
    cudaFuncSetAttribute(k_main, cudaFuncAttributeMaxDynamicSharedMemorySize, SM_TOTAL);

    k_main<<<528, 256, SM_TOTAL>>>(f1, f2, ov);
    k_rows<<<512, 256>>>(ov, (float*)d_out, out_size);
}